// round 4
// baseline (speedup 1.0000x reference)
#include <cuda_runtime.h>
#include <cstdint>

// Problem constants
#define B_      512
#define L_      512
#define KOBS    103
#define H_      512
#define G4      2048          // 4*H
#define KTOT    617           // 103 obs + 2 pos + 512 h
#define KP      620           // padded to multiple of 4
#define KPAD    640           // packed weight row stride (floats)
#define MB      32            // batch rows per cluster (group)
#define NPAIR   16            // MB/2 row-pairs
#define KROW    624           // inpP row stride in float2 (16B-aligned rows)
#define NTHREADS 256
#define NCTAS   128           // 16 clusters x 8 CTAs
#define CLU     8

// Device-global scratch (allocation-free rule: __device__ globals)
__device__ float g_Wpack[G4 * KPAD];   // 5.24 MB packed weights
__device__ float g_bsum[G4];           // b_ih + b_hh, reordered
__device__ float g_hbuf[B_ * H_];      // recurrent h (L2-coherent via cg)
__device__ float g_ybuf[B_ * 2];       // fed-back predicted pos

// ---------------------------------------------------------------------------
// helpers
// ---------------------------------------------------------------------------
__device__ __forceinline__ unsigned long long pk2(float lo, float hi) {
    unsigned long long r;
    asm("mov.b64 %0, {%1, %2};" : "=l"(r) : "f"(lo), "f"(hi));
    return r;
}
__device__ __forceinline__ void upk2(unsigned long long v, float& lo, float& hi) {
    asm("mov.b64 {%0, %1}, %2;" : "=f"(lo), "=f"(hi) : "l"(v));
}
// packed f32x2 FMA: acc = a*b + acc  (2 fp32 lanes per instruction)
#define FMA2(acc, a, b) asm("fma.rn.f32x2 %0, %1, %2, %0;" : "+l"(acc) : "l"(a), "l"(b))

__device__ __forceinline__ void cluster_sync_() {
    asm volatile("barrier.cluster.arrive.aligned;" ::: "memory");
    asm volatile("barrier.cluster.wait.aligned;" ::: "memory");
}

__device__ __forceinline__ float sigf(float v)   { return 1.f / (1.f + __expf(-v)); }
__device__ __forceinline__ float tanhf_(float v) { return 2.f / (1.f + __expf(-2.f * v)) - 1.f; }

// ---------------------------------------------------------------------------
// one-time weight packing: Wpack[rho][k], rho = (rank*4 + gate)*64 + unit
// k<105 -> W_ih[gcol][k]; 105<=k<617 -> W_hh[gcol][k-105]; else 0.
// ---------------------------------------------------------------------------
__global__ void pack_kernel(const float* __restrict__ W_ih,
                            const float* __restrict__ W_hh,
                            const float* __restrict__ b_ih,
                            const float* __restrict__ b_hh) {
    int stride = gridDim.x * blockDim.x;
    for (int idx = blockIdx.x * blockDim.x + threadIdx.x; idx < G4 * KPAD; idx += stride) {
        int rho = idx / KPAD;
        int k   = idx - rho * KPAD;
        int r = rho >> 8;
        int local = rho & 255;
        int q = local >> 6;
        int j = local & 63;
        int gcol = q * H_ + r * 64 + j;
        float v = 0.f;
        if (k < 105)       v = W_ih[gcol * 105 + k];
        else if (k < KTOT) v = W_hh[gcol * H_ + (k - 105)];
        g_Wpack[idx] = v;
        if (k == 0) g_bsum[rho] = b_ih[gcol] + b_hh[gcol];
    }
}

// ---------------------------------------------------------------------------
// persistent recurrent kernel: 16 independent batch groups, 8-CTA clusters
// ---------------------------------------------------------------------------
struct __align__(16) SM {
    float2 inpP[NPAIR][KROW];   // [row-pair][k] : {row2mp, row2mp+1}   79.9 KB
    float  g_s[4][64][33];      // gates [gate][unit][row] (+pad)       33.8 KB
    float  c_s[64][33];         // cell state slice [unit][row] (+pad)   8.4 KB
    float  hm_s[4][H_];         // staged h rows for MLP                 8.2 KB
    float  y1_s[4][64];
    float  y2_s[4][16];
};

__global__ void __launch_bounds__(NTHREADS, 1) __cluster_dims__(CLU, 1, 1)
lstm_kernel(const float* __restrict__ x,  const float* __restrict__ pos,
            const float* __restrict__ h0, const float* __restrict__ c0,
            const float* __restrict__ W1, const float* __restrict__ b1,
            const float* __restrict__ W2, const float* __restrict__ b2,
            const float* __restrict__ W3, const float* __restrict__ b3,
            float* __restrict__ out) {
    extern __shared__ char smraw[];
    SM& sm = *reinterpret_cast<SM*>(smraw);

    const int tid = threadIdx.x;
    const int grp = blockIdx.x >> 3;   // batch group (16)
    const int rnk = blockIdx.x & 7;    // cluster rank = hidden slice
    const int b0  = grp * MB;
    const int q = tid >> 6, j = tid & 63;  // this thread's gate / unit column

    // ---- init state ----
    for (int idx = tid; idx < 64 * MB; idx += NTHREADS) {
        int jj = idx & 63, row = idx >> 6;
        int b = b0 + row, u = rnk * 64 + jj;
        sm.c_s[jj][row] = c0[b * H_ + u];
        __stcg(&g_hbuf[b * H_ + u], h0[b * H_ + u]);
    }
    if (tid < 8) {
        int rr = tid >> 1, o = tid & 1;
        int b = b0 + rnk * 4 + rr;
        __stcg(&g_ybuf[b * 2 + o], pos[b * L_ * 2 + o]);   // pos[:,0,:]
    }
    __threadfence();
    cluster_sync_();

    const float4* wrow = reinterpret_cast<const float4*>(g_Wpack)
                         + (size_t)(rnk * 256 + tid) * (KPAD / 4);
    const float bias = g_bsum[rnk * 256 + tid];

    for (int t = 0; t < L_; t++) {
        // ---- fill input tile: [x_t | y_prev | h_prev] as row-pairs ----
        for (int idx = tid; idx < NPAIR * KP; idx += NTHREADS) {
            int mp = idx / KP;
            int k  = idx - mp * KP;
            int ba = b0 + 2 * mp;
            float va, vb;
            if (k < KOBS) {
                va = x[(ba * L_ + t) * KOBS + k];
                vb = x[((ba + 1) * L_ + t) * KOBS + k];
            } else if (k < 105) {
                va = __ldcg(&g_ybuf[ba * 2 + (k - KOBS)]);
                vb = __ldcg(&g_ybuf[(ba + 1) * 2 + (k - KOBS)]);
            } else if (k < KTOT) {
                va = __ldcg(&g_hbuf[ba * H_ + (k - 105)]);
                vb = __ldcg(&g_hbuf[(ba + 1) * H_ + (k - 105)]);
            } else { va = 0.f; vb = 0.f; }
            sm.inpP[mp][k] = make_float2(va, vb);
        }
        cluster_sync_();   // input tile ready; also fences prior h/y reads vs new writes

        // ---- gate GEMM: this thread = one gate column, 16 row-pairs, K=620 ----
        unsigned long long acc[NPAIR];
        {
            unsigned long long bb = pk2(bias, bias);
            #pragma unroll
            for (int mp = 0; mp < NPAIR; mp++) acc[mp] = bb;
        }
        float4 wv = __ldg(&wrow[0]);
        #pragma unroll 1
        for (int kb = 0; kb < KP / 4; kb++) {
            float4 wn = __ldg(&wrow[kb + 1]);   // prefetch (in-bounds: KPAD padding)
            unsigned long long w0 = pk2(wv.x, wv.x);
            unsigned long long w1 = pk2(wv.y, wv.y);
            unsigned long long w2 = pk2(wv.z, wv.z);
            unsigned long long w3 = pk2(wv.w, wv.w);
            #pragma unroll
            for (int mp = 0; mp < NPAIR; mp++) {
                const ulonglong2* p =
                    reinterpret_cast<const ulonglong2*>(&sm.inpP[mp][kb * 4]);
                ulonglong2 p01 = p[0];
                ulonglong2 p23 = p[1];
                FMA2(acc[mp], w0, p01.x);
                FMA2(acc[mp], w1, p01.y);
                FMA2(acc[mp], w2, p23.x);
                FMA2(acc[mp], w3, p23.y);
            }
            wv = wn;
        }
        #pragma unroll
        for (int mp = 0; mp < NPAIR; mp++) {
            float lo, hi;
            upk2(acc[mp], lo, hi);
            sm.g_s[q][j][2 * mp]     = lo;
            sm.g_s[q][j][2 * mp + 1] = hi;
        }
        __syncthreads();

        // ---- LSTM elementwise update (own 64-unit slice, 32 rows) ----
        {
            int j2 = tid & 63;
            int rb = (tid >> 6) * 8;
            #pragma unroll
            for (int rr = 0; rr < 8; rr++) {
                int row = rb + rr;
                float gi = sm.g_s[0][j2][row];
                float gf = sm.g_s[1][j2][row];
                float gg = sm.g_s[2][j2][row];
                float go = sm.g_s[3][j2][row];
                float c  = sm.c_s[j2][row];
                c = sigf(gf) * c + sigf(gi) * tanhf_(gg);
                float h = sigf(go) * tanhf_(c);
                sm.c_s[j2][row] = c;
                __stcg(&g_hbuf[(b0 + row) * H_ + rnk * 64 + j2], h);
            }
        }
        __threadfence();
        cluster_sync_();   // full h for this group visible

        // ---- MLP head for my 4 rows: 512 -> 64 -> 16 -> 2 (ReLU) ----
        {
            int rbase = b0 + rnk * 4;
            for (int idx = tid; idx < 4 * H_; idx += NTHREADS) {
                int rr = idx >> 9, k = idx & 511;
                sm.hm_s[rr][k] = __ldcg(&g_hbuf[(rbase + rr) * H_ + k]);
            }
            __syncthreads();
            {
                int o = tid & 63, rr = tid >> 6;
                const float4* w1r = reinterpret_cast<const float4*>(W1 + o * H_);
                const float4* hr  = reinterpret_cast<const float4*>(sm.hm_s[rr]);
                float a0 = 0.f, a1 = 0.f, a2 = 0.f, a3 = 0.f;
                #pragma unroll 8
                for (int kk = 0; kk < H_ / 4; kk++) {
                    float4 w  = __ldg(&w1r[kk]);
                    float4 h4 = hr[kk];
                    a0 += w.x * h4.x; a1 += w.y * h4.y;
                    a2 += w.z * h4.z; a3 += w.w * h4.w;
                }
                float v = a0 + a1 + a2 + a3 + __ldg(&b1[o]);
                sm.y1_s[rr][o] = fmaxf(v, 0.f);
            }
            __syncthreads();
            if (tid < 64) {
                int o = tid & 15, rr = tid >> 4;
                float a = __ldg(&b2[o]);
                #pragma unroll
                for (int kk = 0; kk < 64; kk++)
                    a += __ldg(&W2[o * 64 + kk]) * sm.y1_s[rr][kk];
                sm.y2_s[rr][o] = fmaxf(a, 0.f);
            }
            __syncthreads();
            if (tid < 8) {
                int o = tid & 1, rr = tid >> 1;
                float a = __ldg(&b3[o]);
                #pragma unroll
                for (int kk = 0; kk < 16; kk++)
                    a += __ldg(&W3[o * 16 + kk]) * sm.y2_s[rr][kk];
                a = fmaxf(a, 0.f);
                int b = rbase + rr;
                out[(b * L_ + t) * 2 + o] = a;       // predicted_pos[b, t, o]
                __stcg(&g_ybuf[b * 2 + o], a);       // feedback
            }
        }
        __threadfence();
        cluster_sync_();   // y ready for next step's fill
    }

    // ---- final h, c outputs ----
    for (int idx = tid; idx < 64 * MB; idx += NTHREADS) {
        int jj = idx & 63, row = idx >> 6;
        int b = b0 + row, u = rnk * 64 + jj;
        out[B_ * L_ * 2 + b * H_ + u]            = __ldcg(&g_hbuf[b * H_ + u]);
        out[B_ * L_ * 2 + B_ * H_ + b * H_ + u]  = sm.c_s[jj][row];
    }
}

// ---------------------------------------------------------------------------
extern "C" void kernel_launch(void* const* d_in, const int* in_sizes, int n_in,
                              void* d_out, int out_size) {
    const float* x    = (const float*)d_in[0];
    const float* pos  = (const float*)d_in[1];
    const float* h0   = (const float*)d_in[2];
    const float* c0   = (const float*)d_in[3];
    const float* W_ih = (const float*)d_in[4];
    const float* W_hh = (const float*)d_in[5];
    const float* b_ih = (const float*)d_in[6];
    const float* b_hh = (const float*)d_in[7];
    const float* W1   = (const float*)d_in[8];
    const float* b1   = (const float*)d_in[9];
    const float* W2   = (const float*)d_in[10];
    const float* b2   = (const float*)d_in[11];
    const float* W3   = (const float*)d_in[12];
    const float* b3   = (const float*)d_in[13];
    float* out = (float*)d_out;

    pack_kernel<<<256, 256>>>(W_ih, W_hh, b_ih, b_hh);

    cudaFuncSetAttribute(lstm_kernel,
                         cudaFuncAttributeMaxDynamicSharedMemorySize,
                         (int)sizeof(SM));
    lstm_kernel<<<NCTAS, NTHREADS, sizeof(SM)>>>(x, pos, h0, c0,
                                                 W1, b1, W2, b2, W3, b3, out);
}

// round 7
// speedup vs baseline: 1.5552x; 1.5552x over previous
#include <cuda_runtime.h>
#include <cstdint>
#include <cstddef>

// Problem constants
#define B_      512
#define L_      512
#define KOBS    103
#define H_      512
#define G4      2048          // 4*H
#define KXY     108           // x(103) + y(2) + pad(3)
#define KW      620           // total packed K (108 + 512)
#define NKB     (KW/4)        // 155 k-chunks
#define MB      32            // batch rows per cluster group
#define NPAIR   16            // MB/2 row-pairs
#define KROW    624           // inpP row stride in float2 (32B-aligned rows)
#define NTH     512
#define NCTAS   128           // 16 groups x 8-CTA clusters
#define CLU     8

// Device-global scratch (allocation-free rule: __device__ globals)
__device__ float4 g_Wq[NKB + 1][G4];   // k-major packed weights (+1 row for prefetch)
__device__ float  g_bsum[G4];
__device__ float  g_W1t[H_][64];       // W1 transposed [k][o]
__device__ float  g_W2t[64][16];       // W2 transposed [k][o]
__device__ float  g_hbuf[B_ * H_];     // recurrent h (L2-coherent via cg) [R1-proven]
__device__ float  g_ybuf[B_ * 2];      // fed-back predicted pos           [R1-proven]

// ---------------------------------------------------------------------------
// helpers
// ---------------------------------------------------------------------------
__device__ __forceinline__ unsigned long long pk2(float lo, float hi) {
    unsigned long long r;
    asm("mov.b64 %0, {%1, %2};" : "=l"(r) : "f"(lo), "f"(hi));
    return r;
}
__device__ __forceinline__ void upk2(unsigned long long v, float& lo, float& hi) {
    asm("mov.b64 {%0, %1}, %2;" : "=f"(lo), "=f"(hi) : "l"(v));
}
#define FMA2(acc, a, b) asm("fma.rn.f32x2 %0, %1, %2, %0;" : "+l"(acc) : "l"(a), "l"(b))

__device__ __forceinline__ void cluster_sync_() {
    asm volatile("barrier.cluster.arrive.aligned;" ::: "memory");
    asm volatile("barrier.cluster.wait.aligned;" ::: "memory");
}
__device__ __forceinline__ float sigf(float v)   { return 1.f / (1.f + __expf(-v)); }
__device__ __forceinline__ float tanhf_(float v) { return 2.f / (1.f + __expf(-2.f * v)) - 1.f; }

// ---------------------------------------------------------------------------
// one-time packing: Wq[kb][rho] (k-major), bias fold, W1/W2 transpose.
// rho = rnk*256 + c;  c -> gate q = c>>6, unit j = c&63; gcol = q*H + rnk*64 + j
// k' map: 0..102 x, 103..104 y (W_ih cols 0..104), 105..107 zero, 108..619 h
// ---------------------------------------------------------------------------
__global__ void pack_kernel(const float* __restrict__ W_ih, const float* __restrict__ W_hh,
                            const float* __restrict__ b_ih, const float* __restrict__ b_hh,
                            const float* __restrict__ W1,   const float* __restrict__ W2) {
    int stride = gridDim.x * blockDim.x;
    int t0 = blockIdx.x * blockDim.x + threadIdx.x;
    for (int idx = t0; idx < NKB * G4; idx += stride) {
        int kb  = idx >> 11;           // /2048
        int rho = idx & 2047;
        int r = rho >> 8, q = (rho >> 6) & 3, j = rho & 63;
        int gcol = q * H_ + r * 64 + j;
        float v[4];
        #pragma unroll
        for (int z = 0; z < 4; z++) {
            int k = kb * 4 + z;
            float w = 0.f;
            if (k < 105)                     w = W_ih[gcol * 105 + k];
            else if (k >= KXY && k < KW)     w = W_hh[gcol * H_ + (k - KXY)];
            v[z] = w;
        }
        g_Wq[kb][rho] = make_float4(v[0], v[1], v[2], v[3]);
    }
    for (int idx = t0; idx < G4; idx += stride) {
        int r = idx >> 8, q = (idx >> 6) & 3, j = idx & 63;
        int gcol = q * H_ + r * 64 + j;
        g_bsum[idx] = b_ih[gcol] + b_hh[gcol];
        if (idx < 2048) {               // also zero the prefetch guard row
            g_Wq[NKB][idx] = make_float4(0.f, 0.f, 0.f, 0.f);
        }
    }
    for (int idx = t0; idx < H_ * 64; idx += stride) {
        int k = idx >> 6, o = idx & 63;
        g_W1t[k][o] = W1[o * H_ + k];
    }
    for (int idx = t0; idx < 64 * 16; idx += stride) {
        int k = idx >> 4, o = idx & 15;
        g_W2t[k][o] = W2[o * 64 + k];
    }
}

// ---------------------------------------------------------------------------
// persistent recurrent kernel: 16 groups x 8-CTA clusters, 512 thr/CTA
// ---------------------------------------------------------------------------
struct __align__(16) SM {
    float2 inpP[NPAIR][KROW];   // [row-pair][k'] full input tile     79.9 KB
    float  g_s[4][64][33];      // gates [gate][unit][row] (+pad)     33.0 KB
    float  c_s[64][33];         // cell state slice                    8.3 KB
    float  hm_s[4][H_];         // staged h rows for MLP               8.2 KB
    float  y1[4][64];
    float  y2[4][16];
};

__global__ void __launch_bounds__(NTH, 1) __cluster_dims__(CLU, 1, 1)
lstm_kernel(const float* __restrict__ x,  const float* __restrict__ pos,
            const float* __restrict__ h0, const float* __restrict__ c0,
            const float* __restrict__ b1, const float* __restrict__ b2,
            const float* __restrict__ W3, const float* __restrict__ b3,
            float* __restrict__ out) {
    extern __shared__ char smraw[];
    SM& sm = *reinterpret_cast<SM*>(smraw);

    const int tid = threadIdx.x;
    const int grp = blockIdx.x >> 3;   // batch group (16)
    const int rnk = blockIdx.x & 7;    // cluster rank = hidden slice
    const int b0  = grp * MB;

    // ---- init state (R1-proven path) ----
    for (int idx = tid; idx < 64 * MB; idx += NTH) {
        int u = idx & 63, row = idx >> 6;
        int b = b0 + row, ug = rnk * 64 + u;
        sm.c_s[u][row] = c0[b * H_ + ug];
        __stcg(&g_hbuf[b * H_ + ug], h0[b * H_ + ug]);
    }
    if (tid < 8) {
        int rr = tid >> 1, o = tid & 1;
        int b = b0 + rnk * 4 + rr;
        __stcg(&g_ybuf[b * 2 + o], pos[b * L_ * 2 + o]);   // pos[:,0,:]
    }
    __threadfence();
    cluster_sync_();

    // GEMM thread mapping: column c (256 per rank), half -> which 8 row-pairs
    const int c    = tid & 255;
    const int half = tid >> 8;
    const int mpb  = half * 8;
    const int q    = c >> 6, jj = c & 63;
    const int wrho = rnk * 256 + c;
    const float bias = g_bsum[wrho];

    // MLP constants hoisted out of the t-loop
    float b1v = 0.f, b2v = 0.f, b3v = 0.f, w3r[16];
    if (tid < 256) b1v = __ldg(&b1[tid & 63]);
    if (tid < 64)  b2v = __ldg(&b2[tid & 15]);
    if (tid < 8) {
        b3v = __ldg(&b3[tid & 1]);
        #pragma unroll
        for (int kk = 0; kk < 16; kk++) w3r[kk] = __ldg(&W3[(tid & 1) * 16 + kk]);
    }

    for (int t = 0; t < L_; t++) {
        // ---- fill input tile: [x_t | y_prev | pad | h_prev] as row-pairs ----
        for (int idx = tid; idx < NPAIR * KW; idx += NTH) {
            int mp = idx / KW;
            int k  = idx - mp * KW;
            int ba = b0 + 2 * mp;
            float va, vb;
            if (k < KOBS) {
                va = x[(ba * L_ + t) * KOBS + k];
                vb = x[((ba + 1) * L_ + t) * KOBS + k];
            } else if (k < 105) {
                va = __ldcg(&g_ybuf[ba * 2 + (k - KOBS)]);
                vb = __ldcg(&g_ybuf[(ba + 1) * 2 + (k - KOBS)]);
            } else if (k < KXY) {
                va = 0.f; vb = 0.f;
            } else {
                va = __ldcg(&g_hbuf[ba * H_ + (k - KXY)]);
                vb = __ldcg(&g_hbuf[(ba + 1) * H_ + (k - KXY)]);
            }
            sm.inpP[mp][k] = make_float2(va, vb);
        }
        cluster_sync_();   // input tiles ready cluster-wide (incl. __syncthreads effect)

        // ---- gate GEMM: 1 column x 8 row-pairs, K = 620, k-major weights ----
        unsigned long long acc[8];
        {
            unsigned long long bb = pk2(bias, bias);
            #pragma unroll
            for (int m = 0; m < 8; m++) acc[m] = bb;
        }
        float4 wv = __ldg(&g_Wq[0][wrho]);
        #pragma unroll 2
        for (int kb = 0; kb < NKB; kb++) {
            float4 wn = __ldg(&g_Wq[kb + 1][wrho]);     // prefetch (guard row zeroed)
            unsigned long long w0 = pk2(wv.x, wv.x), w1 = pk2(wv.y, wv.y);
            unsigned long long w2 = pk2(wv.z, wv.z), w3 = pk2(wv.w, wv.w);
            #pragma unroll
            for (int m = 0; m < 8; m++) {
                const ulonglong2* p =
                    reinterpret_cast<const ulonglong2*>(&sm.inpP[mpb + m][kb * 4]);
                ulonglong2 p01 = p[0], p23 = p[1];
                FMA2(acc[m], w0, p01.x); FMA2(acc[m], w1, p01.y);
                FMA2(acc[m], w2, p23.x); FMA2(acc[m], w3, p23.y);
            }
            wv = wn;
        }
        #pragma unroll
        for (int m = 0; m < 8; m++) {
            float lo, hi;
            upk2(acc[m], lo, hi);
            int mp = mpb + m;
            sm.g_s[q][jj][2 * mp]     = lo;
            sm.g_s[q][jj][2 * mp + 1] = hi;
        }
        __syncthreads();

        // ---- LSTM elementwise update (each thread: 1 unit x 4 rows) ----
        {
            int j2 = tid & 63;
            int rb = (tid >> 6) * 4;
            #pragma unroll
            for (int rr = 0; rr < 4; rr++) {
                int row = rb + rr;
                float gi = sm.g_s[0][j2][row];
                float gf = sm.g_s[1][j2][row];
                float gg = sm.g_s[2][j2][row];
                float go = sm.g_s[3][j2][row];
                float cc = sm.c_s[j2][row];
                cc = sigf(gf) * cc + sigf(gi) * tanhf_(gg);
                float h = sigf(go) * tanhf_(cc);
                sm.c_s[j2][row] = cc;
                __stcg(&g_hbuf[(b0 + row) * H_ + rnk * 64 + j2], h);
            }
        }
        __threadfence();
        cluster_sync_();   // full h for this group visible

        // ---- MLP head for this rank's 4 rows: 512 -> 64 -> 16 -> 2 ----
        {
            int rbase = b0 + rnk * 4;
            for (int idx = tid; idx < 4 * H_; idx += NTH) {
                int rr = idx >> 9, k = idx & 511;
                sm.hm_s[rr][k] = __ldcg(&g_hbuf[(rbase + rr) * H_ + k]);
            }
            __syncthreads();
            if (tid < 256) {
                int o = tid & 63, rr = tid >> 6;
                const float* hr = sm.hm_s[rr];
                float a0 = 0.f, a1 = 0.f, a2 = 0.f, a3 = 0.f;
                #pragma unroll 8
                for (int k = 0; k < H_; k += 4) {
                    a0 += g_W1t[k][o]     * hr[k];
                    a1 += g_W1t[k + 1][o] * hr[k + 1];
                    a2 += g_W1t[k + 2][o] * hr[k + 2];
                    a3 += g_W1t[k + 3][o] * hr[k + 3];
                }
                sm.y1[rr][o] = fmaxf(a0 + a1 + a2 + a3 + b1v, 0.f);
            }
            __syncthreads();
            if (tid < 64) {
                int o = tid & 15, rr = tid >> 4;
                float a = b2v;
                #pragma unroll
                for (int kk = 0; kk < 64; kk++) a += g_W2t[kk][o] * sm.y1[rr][kk];
                sm.y2[rr][o] = fmaxf(a, 0.f);
            }
            __syncthreads();
            if (tid < 8) {
                int o = tid & 1, rr = tid >> 1;
                float a = b3v;
                #pragma unroll
                for (int kk = 0; kk < 16; kk++) a += w3r[kk] * sm.y2[rr][kk];
                a = fmaxf(a, 0.f);
                int b = rbase + rr;
                out[(b * L_ + t) * 2 + o] = a;       // predicted_pos[b, t, o]
                __stcg(&g_ybuf[b * 2 + o], a);       // feedback
            }
        }
        __threadfence();
        cluster_sync_();   // y ready for next step's fill
    }

    // ---- final h, c outputs ----
    for (int idx = tid; idx < 64 * MB; idx += NTH) {
        int u = idx & 63, row = idx >> 6;
        int b = b0 + row, ug = rnk * 64 + u;
        out[B_ * L_ * 2 + b * H_ + ug]            = __ldcg(&g_hbuf[b * H_ + ug]);
        out[B_ * L_ * 2 + B_ * H_ + b * H_ + ug]  = sm.c_s[u][row];
    }
}

// ---------------------------------------------------------------------------
extern "C" void kernel_launch(void* const* d_in, const int* in_sizes, int n_in,
                              void* d_out, int out_size) {
    const float* x    = (const float*)d_in[0];
    const float* pos  = (const float*)d_in[1];
    const float* h0   = (const float*)d_in[2];
    const float* c0   = (const float*)d_in[3];
    const float* W_ih = (const float*)d_in[4];
    const float* W_hh = (const float*)d_in[5];
    const float* b_ih = (const float*)d_in[6];
    const float* b_hh = (const float*)d_in[7];
    const float* W1   = (const float*)d_in[8];
    const float* b1   = (const float*)d_in[9];
    const float* W2   = (const float*)d_in[10];
    const float* b2   = (const float*)d_in[11];
    const float* W3   = (const float*)d_in[12];
    const float* b3   = (const float*)d_in[13];
    float* out = (float*)d_out;

    pack_kernel<<<256, 256>>>(W_ih, W_hh, b_ih, b_hh, W1, W2);

    cudaFuncSetAttribute(lstm_kernel,
                         cudaFuncAttributeMaxDynamicSharedMemorySize,
                         (int)sizeof(SM));
    lstm_kernel<<<NCTAS, NTH, sizeof(SM)>>>(x, pos, h0, c0,
                                            b1, b2, W3, b3, out);
}